// round 4
// baseline (speedup 1.0000x reference)
#include <cuda_runtime.h>
#include <cstdint>

// Problem constants
#define NB     2
#define CIN    256
#define NTOK   4096
#define NH     8
#define DH     64
#define CINNER 512         // NH*DH
#define CQKV   1536        // 3*CINNER

// Scratch (allocation-free rule: __device__ globals)
__device__ float g_qkv[NB * CQKV * NTOK];            // [B][1536][N]
__device__ float g_norms[2 * NB * NH * NTOK];        // q2 then k2
__device__ float g_ao[NB * CINNER * NTOK];           // attention output [B][512][N]

// ---------------------------------------------------------------------------
// mma.sync tf32 helpers (sm_80 feature set -> works on base sm_103 target)
// ---------------------------------------------------------------------------
__device__ __forceinline__ uint32_t tf32r(float f) {
    uint32_t u;
    asm("cvt.rna.tf32.f32 %0, %1;" : "=r"(u) : "f"(f));
    return u;
}

__device__ __forceinline__ void mma8(float c[4], const uint32_t a[4],
                                     uint32_t b0, uint32_t b1) {
    asm volatile(
        "mma.sync.aligned.m16n8k8.row.col.f32.tf32.tf32.f32 "
        "{%0,%1,%2,%3}, {%4,%5,%6,%7}, {%8,%9}, {%0,%1,%2,%3};"
        : "+f"(c[0]), "+f"(c[1]), "+f"(c[2]), "+f"(c[3])
        : "r"(a[0]), "r"(a[1]), "r"(a[2]), "r"(a[3]), "r"(b0), "r"(b1));
}

// ---------------------------------------------------------------------------
// 3xtf32 tensor-core GEMM: Y[b][o][n] = sum_c W[o][c] * X[b][c][n]
// Computed as Y^T[n][o]: A = X^T (M=n), B = W (N=o). fp32-level accuracy via
// hi/lo split (y ~= ah*bh + ah*bl + al*bh).
// CTA: 256 thr = 8 warps; tile 64(n) x 128(o); warp = 32(n) x 32(o); kTile=32.
// ---------------------------------------------------------------------------
__global__ void __launch_bounds__(256, 2) gemm_tc_kernel(
    const float* __restrict__ W,  // [M][K]
    const float* __restrict__ X,  // [B][K][NTOK]
    float* __restrict__ Y,        // [B][M][NTOK]
    int K, long xStride, long yStride)
{
    extern __shared__ float sm[];
    float* XS = sm;               // [c(32)][132] : (hi,lo) pairs at 2n
    float* WS = sm + 32 * 132;    // [o(128)][68] : (hi,lo) pairs at 2c

    const int tid = threadIdx.x;
    const int lane = tid & 31, w = tid >> 5;
    const int quad = lane & 3, g = lane >> 2;
    const int wn = w >> 2, wo = w & 3;       // wn 0..1, wo 0..3
    const int nblk = blockIdx.x * 64;
    const int oblk = blockIdx.y * 128;
    const float* Xb = X + (long)blockIdx.z * xStride;
    float*       Yb = Y + (long)blockIdx.z * yStride;

    float acc[2][4][4];
    #pragma unroll
    for (int mt = 0; mt < 2; mt++)
        #pragma unroll
        for (int ot = 0; ot < 4; ot++)
            #pragma unroll
            for (int r = 0; r < 4; r++) acc[mt][ot][r] = 0.f;

    for (int kc = 0; kc < K; kc += 32) {
        __syncthreads();
        // ---- stage X tile (32 c-rows x 64 n), hi/lo split ----
        {
            int cr = tid >> 3, n0 = (tid & 7) * 8;
            const float* src = Xb + (long)(kc + cr) * NTOK + nblk + n0;
            float4 v0 = *(const float4*)src;
            float4 v1 = *(const float4*)(src + 4);
            float vv[8] = {v0.x, v0.y, v0.z, v0.w, v1.x, v1.y, v1.z, v1.w};
            float* dst = XS + cr * 132 + 2 * n0;
            #pragma unroll
            for (int e = 0; e < 8; e++) {
                float hi = __uint_as_float(tf32r(vv[e]));
                *(float2*)(dst + 2 * e) = make_float2(hi, vv[e] - hi);
            }
        }
        // ---- stage W tile (128 o-rows x 32 c), hi/lo split ----
        {
            int o = tid >> 1, c0 = (tid & 1) * 16;
            const float* src = W + (long)(oblk + o) * K + kc + c0;
            float* dst = WS + o * 68 + 2 * c0;
            #pragma unroll
            for (int f = 0; f < 4; f++) {
                float4 v = *(const float4*)(src + 4 * f);
                float vv[4] = {v.x, v.y, v.z, v.w};
                #pragma unroll
                for (int e = 0; e < 4; e++) {
                    float hi = __uint_as_float(tf32r(vv[e]));
                    *(float2*)(dst + 2 * (4 * f + e)) = make_float2(hi, vv[e] - hi);
                }
            }
        }
        __syncthreads();

        #pragma unroll
        for (int ks = 0; ks < 4; ks++) {
            // A frags (from X^T): a0=(n:g, c:quad) a1=(n+8) a2=(c+4) a3=(both)
            uint32_t ah[2][4], al[2][4];
            #pragma unroll
            for (int mt = 0; mt < 2; mt++) {
                int n = 32 * wn + 16 * mt + g;
                const float* base = XS + (8 * ks + quad) * 132 + 2 * n;
                float2 p0 = *(const float2*)(base);
                float2 p1 = *(const float2*)(base + 16);
                float2 p2 = *(const float2*)(base + 4 * 132);
                float2 p3 = *(const float2*)(base + 4 * 132 + 16);
                ah[mt][0] = __float_as_uint(p0.x); al[mt][0] = __float_as_uint(p0.y);
                ah[mt][1] = __float_as_uint(p1.x); al[mt][1] = __float_as_uint(p1.y);
                ah[mt][2] = __float_as_uint(p2.x); al[mt][2] = __float_as_uint(p2.y);
                ah[mt][3] = __float_as_uint(p3.x); al[mt][3] = __float_as_uint(p3.y);
            }
            #pragma unroll
            for (int ot = 0; ot < 4; ot++) {
                int o = 32 * wo + 8 * ot + g;
                const float* base = WS + o * 68 + 2 * (8 * ks + quad);
                float2 b0 = *(const float2*)(base);        // c = 8ks+quad
                float2 b1 = *(const float2*)(base + 8);    // c+4
                uint32_t b0h = __float_as_uint(b0.x), b0l = __float_as_uint(b0.y);
                uint32_t b1h = __float_as_uint(b1.x), b1l = __float_as_uint(b1.y);
                #pragma unroll
                for (int mt = 0; mt < 2; mt++) {
                    mma8(acc[mt][ot], al[mt], b0h, b1h);
                    mma8(acc[mt][ot], ah[mt], b0l, b1l);
                    mma8(acc[mt][ot], ah[mt], b0h, b1h);
                }
            }
        }
    }

    // epilogue: c0=(n:g, o:2quad) c1=(o+1) c2=(n+8) c3=(o+1,n+8)
    #pragma unroll
    for (int mt = 0; mt < 2; mt++)
        #pragma unroll
        for (int ot = 0; ot < 4; ot++) {
            int n = nblk + 32 * wn + 16 * mt + g;
            int o = oblk + 32 * wo + 8 * ot + 2 * quad;
            Yb[(long)o * NTOK + n]           = acc[mt][ot][0];
            Yb[(long)(o + 1) * NTOK + n]     = acc[mt][ot][1];
            Yb[(long)o * NTOK + n + 8]       = acc[mt][ot][2];
            Yb[(long)(o + 1) * NTOK + n + 8] = acc[mt][ot][3];
        }
}

// ---------------------------------------------------------------------------
// Norms: q2[b][h][n], k2[b][h][n]
// ---------------------------------------------------------------------------
__global__ void __launch_bounds__(256) norms_kernel()
{
    int idx = blockIdx.x * 256 + threadIdx.x;
    int n = idx & (NTOK - 1);
    int t = idx >> 12;
    int h = t & 7;
    int pb = t >> 3;
    int part = pb & 1;
    int b = pb >> 1;
    const float* p = g_qkv + ((long)(b * CQKV + part * CINNER + h * DH)) * NTOK + n;
    float s = 0.f;
    #pragma unroll
    for (int d = 0; d < DH; d++) { float v = p[(long)d * NTOK]; s = fmaf(v, v, s); }
    g_norms[(long)part * (NB * NH * NTOK) + (long)(b * NH + h) * NTOK + n] = s;
}

// ---------------------------------------------------------------------------
// Flash distance attention via mma.sync tf32.
// CTA = 256 threads = 8 warps; each warp owns 16 query rows (128 q / CTA).
// Fixed-shift softmax (scores bounded) -> no running max, no rescale.
// ---------------------------------------------------------------------------
__global__ void __launch_bounds__(256, 2) attn_mma_kernel()
{
    __shared__ uint32_t KF[8 * 516];
    __shared__ uint32_t VF[8 * 544];
    __shared__ float    k2s[64];

    const int tid  = threadIdx.x;
    const int wid  = tid >> 5;
    const int lane = tid & 31;
    const int quad = lane & 3;
    const int g    = lane >> 2;
    const int n0   = blockIdx.x * 128;
    const int h = blockIdx.y, b = blockIdx.z;
    const int bh = b * NH + h;

    const float* qb  = g_qkv + (long)(b * CQKV + h * DH) * NTOK;
    const float* kb  = g_qkv + (long)(b * CQKV + CINNER + h * DH) * NTOK;
    const float* vb  = g_qkv + (long)(b * CQKV + 2 * CINNER + h * DH) * NTOK;
    const float* k2g = g_norms + (long)NB * NH * NTOK + (long)bh * NTOK;

    const int i0 = n0 + wid * 16 + g;

    uint32_t aq[8][4];
    #pragma unroll
    for (int ks = 0; ks < 8; ks++) {
        int d = quad + 8 * ks;
        aq[ks][0] = tf32r(qb[(long)d * NTOK + i0]);
        aq[ks][1] = tf32r(qb[(long)d * NTOK + i0 + 8]);
        aq[ks][2] = tf32r(qb[(long)(d + 4) * NTOK + i0]);
        aq[ks][3] = tf32r(qb[(long)(d + 4) * NTOK + i0 + 8]);
    }
    const float q2a = g_norms[(long)bh * NTOK + i0];
    const float q2b = g_norms[(long)bh * NTOK + i0 + 8];

    constexpr float LOG2E  = 1.4426950408889634f;
    constexpr float NSHIFT = -12.0f * LOG2E;

    float o[8][4];
    #pragma unroll
    for (int nt = 0; nt < 8; nt++)
        #pragma unroll
        for (int r = 0; r < 4; r++) o[nt][r] = 0.f;
    float lsum0 = 0.f, lsum1 = 0.f;

    const int srcA = (lane & ~3) | (quad >> 1);
    const int srcB = srcA + 2;

    for (int kt = 0; kt < NTOK / 64; kt++) {
        const int nk = kt * 64;
        __syncthreads();

        // ---- stage K tile into fragment order (RNA-rounded: feeds exp) ----
        #pragma unroll
        for (int it = 0; it < 4; it++) {
            int idx = tid + it * 256;
            int d = idx >> 4, j4 = (idx & 15) << 2;
            float4 kv = *(const float4*)(kb + (long)d * NTOK + nk + j4);
            int base = (d >> 3) * 64 + (d & 3) * 2 + ((d >> 2) & 1);
            float v4[4] = {kv.x, kv.y, kv.z, kv.w};
            #pragma unroll
            for (int r = 0; r < 4; r++) {
                int j = j4 + r;
                KF[(j >> 3) * 516 + base + (j & 7) * 8] = tf32r(v4[r]);
            }
        }
        // ---- stage V tile (raw fp32 bits; mma truncates to tf32) ----
        #pragma unroll
        for (int it = 0; it < 4; it++) {
            int idx = tid + it * 256;
            int dd = idx >> 4, j4 = (idx & 15) << 2;
            float4 vv = *(const float4*)(vb + (long)dd * NTOK + nk + j4);
            int base = (dd >> 3) * 544 + (dd & 7) * 8;
            float v4[4] = {vv.x, vv.y, vv.z, vv.w};
            #pragma unroll
            for (int r = 0; r < 4; r++) {
                int j = j4 + r;
                VF[base + (j >> 3) * 68 + (j & 3) * 2 + ((j >> 2) & 1)] =
                    __float_as_uint(v4[r]);
            }
        }
        if (tid < 64) k2s[tid] = k2g[nk + tid];
        __syncthreads();

        #pragma unroll
        for (int nt = 0; nt < 8; nt++) {
            float c[4] = {0.f, 0.f, 0.f, 0.f};
            const uint32_t* kfp = KF + nt * 516 + lane * 2;
            #pragma unroll
            for (int ks = 0; ks < 8; ks++) {
                uint2 bb = *(const uint2*)(kfp + ks * 64);
                mma8(c, aq[ks], bb.x, bb.y);
            }
            float k2c0 = k2s[8 * nt + 2 * quad];
            float k2c1 = k2s[8 * nt + 2 * quad + 1];
            float p[4];
            {
                float d2, s;
                d2 = fmaxf(q2a + k2c0 - 2.f * c[0], 0.f);
                asm("sqrt.approx.f32 %0, %1;" : "=f"(s) : "f"(d2));
                asm("ex2.approx.f32 %0, %1;" : "=f"(p[0]) : "f"(fmaf(s, LOG2E, NSHIFT)));
                d2 = fmaxf(q2a + k2c1 - 2.f * c[1], 0.f);
                asm("sqrt.approx.f32 %0, %1;" : "=f"(s) : "f"(d2));
                asm("ex2.approx.f32 %0, %1;" : "=f"(p[1]) : "f"(fmaf(s, LOG2E, NSHIFT)));
                d2 = fmaxf(q2b + k2c0 - 2.f * c[2], 0.f);
                asm("sqrt.approx.f32 %0, %1;" : "=f"(s) : "f"(d2));
                asm("ex2.approx.f32 %0, %1;" : "=f"(p[2]) : "f"(fmaf(s, LOG2E, NSHIFT)));
                d2 = fmaxf(q2b + k2c1 - 2.f * c[3], 0.f);
                asm("sqrt.approx.f32 %0, %1;" : "=f"(s) : "f"(d2));
                asm("ex2.approx.f32 %0, %1;" : "=f"(p[3]) : "f"(fmaf(s, LOG2E, NSHIFT)));
            }
            lsum0 += p[0] + p[1];
            lsum1 += p[2] + p[3];

            // C-frag -> A-frag transpose via quad shuffles (raw bits, HW truncates)
            uint32_t up0 = __float_as_uint(p[0]), up1 = __float_as_uint(p[1]);
            uint32_t up2 = __float_as_uint(p[2]), up3 = __float_as_uint(p[3]);
            uint32_t x0 = __shfl_sync(0xffffffffu, up0, srcA);
            uint32_t x1 = __shfl_sync(0xffffffffu, up1, srcA);
            uint32_t x2 = __shfl_sync(0xffffffffu, up2, srcA);
            uint32_t x3 = __shfl_sync(0xffffffffu, up3, srcA);
            uint32_t y0 = __shfl_sync(0xffffffffu, up0, srcB);
            uint32_t y1 = __shfl_sync(0xffffffffu, up1, srcB);
            uint32_t y2 = __shfl_sync(0xffffffffu, up2, srcB);
            uint32_t y3 = __shfl_sync(0xffffffffu, up3, srcB);
            uint32_t ap[4];
            ap[0] = (quad & 1) ? x1 : x0;
            ap[1] = (quad & 1) ? x3 : x2;
            ap[2] = (quad & 1) ? y1 : y0;
            ap[3] = (quad & 1) ? y3 : y2;

            const uint32_t* vfp = VF + nt * 68 + lane * 2;
            #pragma unroll
            for (int ddnt = 0; ddnt < 8; ddnt++) {
                uint2 vv = *(const uint2*)(vfp + ddnt * 544);
                mma8(o[ddnt], ap, vv.x, vv.y);
            }
        }
    }

    lsum0 += __shfl_xor_sync(0xffffffffu, lsum0, 1);
    lsum0 += __shfl_xor_sync(0xffffffffu, lsum0, 2);
    lsum1 += __shfl_xor_sync(0xffffffffu, lsum1, 1);
    lsum1 += __shfl_xor_sync(0xffffffffu, lsum1, 2);
    const float inv0 = 1.f / lsum0;
    const float inv1 = 1.f / lsum1;

    float* aob = g_ao + (long)(b * CINNER + h * DH) * NTOK;
    #pragma unroll
    for (int nt = 0; nt < 8; nt++) {
        int dd = 8 * nt + 2 * quad;
        aob[(long)dd * NTOK + i0]           = o[nt][0] * inv0;
        aob[(long)(dd + 1) * NTOK + i0]     = o[nt][1] * inv0;
        aob[(long)dd * NTOK + i0 + 8]       = o[nt][2] * inv1;
        aob[(long)(dd + 1) * NTOK + i0 + 8] = o[nt][3] * inv1;
    }
}

// ---------------------------------------------------------------------------
extern "C" void kernel_launch(void* const* d_in, const int* in_sizes, int n_in,
                              void* d_out, int out_size)
{
    (void)in_sizes; (void)n_in; (void)out_size;
    const float* fmap  = (const float*)d_in[0];   // [2,256,64,64]
    const float* w_qkv = (const float*)d_in[1];   // [1536,256]
    const float* w_out = (const float*)d_in[2];   // [256,512]
    float* out = (float*)d_out;                   // [2,256,64,64]

    void* qkvPtr = nullptr;
    void* aoPtr  = nullptr;
    cudaGetSymbolAddress(&qkvPtr, g_qkv);
    cudaGetSymbolAddress(&aoPtr,  g_ao);

    const int gemmSmem = (32 * 132 + 128 * 68) * (int)sizeof(float);  // 51712
    cudaFuncSetAttribute(gemm_tc_kernel,
                         cudaFuncAttributeMaxDynamicSharedMemorySize, gemmSmem);

    // K1: QKV projection  [1536,256] @ [2,256,4096] -> g_qkv (3xtf32)
    {
        dim3 grid(NTOK / 64, CQKV / 128, NB);
        gemm_tc_kernel<<<grid, 256, gemmSmem>>>(w_qkv, fmap, (float*)qkvPtr,
                                                CIN, (long)CIN * NTOK, (long)CQKV * NTOK);
    }
    // K2: norms
    norms_kernel<<<(NB * NH * 2 * NTOK) / 256, 256>>>();

    // K3: tensor-core (mma.sync tf32) attention
    {
        dim3 grid(NTOK / 128, NH, NB);
        attn_mma_kernel<<<grid, 256>>>();
    }
    // K4: output projection [256,512] @ [2,512,4096] -> out (3xtf32)
    {
        dim3 grid(NTOK / 64, CIN / 128, NB);
        gemm_tc_kernel<<<grid, 256, gemmSmem>>>(w_out, (const float*)aoPtr, out,
                                                CINNER, (long)CINNER * NTOK, (long)CIN * NTOK);
    }
}

// round 5
// speedup vs baseline: 1.0349x; 1.0349x over previous
#include <cuda_runtime.h>
#include <cstdint>

// Problem constants
#define NB     2
#define CIN    256
#define NTOK   4096
#define NH     8
#define DH     64
#define CINNER 512         // NH*DH
#define CQKV   1536        // 3*CINNER

// Scratch (allocation-free rule: __device__ globals)
__device__ float g_qkv[NB * CQKV * NTOK];            // [B][1536][N]
__device__ float g_norms[2 * NB * NH * NTOK];        // q2 then k2
__device__ float g_ao[NB * CINNER * NTOK];           // attention output [B][512][N]

// ---------------------------------------------------------------------------
// mma.sync tf32 helpers
// ---------------------------------------------------------------------------
__device__ __forceinline__ uint32_t tf32r(float f) {
    uint32_t u;
    asm("cvt.rna.tf32.f32 %0, %1;" : "=r"(u) : "f"(f));
    return u;
}

__device__ __forceinline__ void mma8(float c[4], const uint32_t a[4],
                                     uint32_t b0, uint32_t b1) {
    asm volatile(
        "mma.sync.aligned.m16n8k8.row.col.f32.tf32.tf32.f32 "
        "{%0,%1,%2,%3}, {%4,%5,%6,%7}, {%8,%9}, {%0,%1,%2,%3};"
        : "+f"(c[0]), "+f"(c[1]), "+f"(c[2]), "+f"(c[3])
        : "r"(a[0]), "r"(a[1]), "r"(a[2]), "r"(a[3]), "r"(b0), "r"(b1));
}

// ---------------------------------------------------------------------------
// 3xtf32 tensor-core GEMM, software-pipelined (reg prefetch of next k-tile).
// Y[b][o][n] = sum_c W[o][c] * X[b][c][n], computed as Y^T: A=X^T, B=W.
// CTA: 256 thr = 8 warps; tile 64(n) x 128(o); warp = 32(n) x 32(o); kTile=32.
// ---------------------------------------------------------------------------
__global__ void __launch_bounds__(256, 2) gemm_tc_kernel(
    const float* __restrict__ W,  // [M][K]
    const float* __restrict__ X,  // [B][K][NTOK]
    float* __restrict__ Y,        // [B][M][NTOK]
    int K, long xStride, long yStride)
{
    extern __shared__ float sm[];
    float* XS = sm;               // [c(32)][132] : (hi,lo) pairs at 2n
    float* WS = sm + 32 * 132;    // [o(128)][68] : (hi,lo) pairs at 2c

    const int tid = threadIdx.x;
    const int lane = tid & 31, w = tid >> 5;
    const int quad = lane & 3, g = lane >> 2;
    const int wn = w >> 2, wo = w & 3;
    const int nblk = blockIdx.x * 64;
    const int oblk = blockIdx.y * 128;
    const float* Xb = X + (long)blockIdx.z * xStride;
    float*       Yb = Y + (long)blockIdx.z * yStride;

    // per-thread gmem staging coordinates
    const int xcr = tid >> 3, xn0 = (tid & 7) * 8;          // X: row c, 8 n's
    const int wor = tid >> 1, wc0 = (tid & 1) * 16;         // W: row o, 16 c's
    const float* xsrc = Xb + (long)xcr * NTOK + nblk + xn0;
    const float* wsrc = W + (long)(oblk + wor) * K + wc0;

    float acc[2][4][4];
    #pragma unroll
    for (int mt = 0; mt < 2; mt++)
        #pragma unroll
        for (int ot = 0; ot < 4; ot++)
            #pragma unroll
            for (int r = 0; r < 4; r++) acc[mt][ot][r] = 0.f;

    // prologue prefetch (kc = 0)
    float4 xr0 = *(const float4*)(xsrc);
    float4 xr1 = *(const float4*)(xsrc + 4);
    float4 wr0 = *(const float4*)(wsrc);
    float4 wr1 = *(const float4*)(wsrc + 4);
    float4 wr2 = *(const float4*)(wsrc + 8);
    float4 wr3 = *(const float4*)(wsrc + 12);

    for (int kc = 0; kc < K; kc += 32) {
        __syncthreads();   // previous compute done reading smem
        // ---- store staged regs with hi/lo split ----
        {
            float vv[8] = {xr0.x, xr0.y, xr0.z, xr0.w, xr1.x, xr1.y, xr1.z, xr1.w};
            float* dst = XS + xcr * 132 + 2 * xn0;
            #pragma unroll
            for (int e = 0; e < 8; e++) {
                float hi = __uint_as_float(tf32r(vv[e]));
                *(float2*)(dst + 2 * e) = make_float2(hi, vv[e] - hi);
            }
        }
        {
            float vv[16] = {wr0.x, wr0.y, wr0.z, wr0.w, wr1.x, wr1.y, wr1.z, wr1.w,
                            wr2.x, wr2.y, wr2.z, wr2.w, wr3.x, wr3.y, wr3.z, wr3.w};
            float* dst = WS + wor * 68 + 2 * wc0;
            #pragma unroll
            for (int e = 0; e < 16; e++) {
                float hi = __uint_as_float(tf32r(vv[e]));
                *(float2*)(dst + 2 * e) = make_float2(hi, vv[e] - hi);
            }
        }
        __syncthreads();

        // ---- prefetch next k-tile (hidden under compute) ----
        if (kc + 32 < K) {
            const float* xs = xsrc + (long)(kc + 32) * NTOK;
            const float* ws = wsrc + kc + 32;
            xr0 = *(const float4*)(xs);
            xr1 = *(const float4*)(xs + 4);
            wr0 = *(const float4*)(ws);
            wr1 = *(const float4*)(ws + 4);
            wr2 = *(const float4*)(ws + 8);
            wr3 = *(const float4*)(ws + 12);
        }

        // ---- compute 4 ks steps ----
        #pragma unroll
        for (int ks = 0; ks < 4; ks++) {
            uint32_t ah[2][4], al[2][4];
            #pragma unroll
            for (int mt = 0; mt < 2; mt++) {
                int n = 32 * wn + 16 * mt + g;
                const float* base = XS + (8 * ks + quad) * 132 + 2 * n;
                float2 p0 = *(const float2*)(base);
                float2 p1 = *(const float2*)(base + 16);
                float2 p2 = *(const float2*)(base + 4 * 132);
                float2 p3 = *(const float2*)(base + 4 * 132 + 16);
                ah[mt][0] = __float_as_uint(p0.x); al[mt][0] = __float_as_uint(p0.y);
                ah[mt][1] = __float_as_uint(p1.x); al[mt][1] = __float_as_uint(p1.y);
                ah[mt][2] = __float_as_uint(p2.x); al[mt][2] = __float_as_uint(p2.y);
                ah[mt][3] = __float_as_uint(p3.x); al[mt][3] = __float_as_uint(p3.y);
            }
            #pragma unroll
            for (int ot = 0; ot < 4; ot++) {
                int o = 32 * wo + 8 * ot + g;
                const float* base = WS + o * 68 + 2 * (8 * ks + quad);
                float2 b0 = *(const float2*)(base);
                float2 b1 = *(const float2*)(base + 8);
                uint32_t b0h = __float_as_uint(b0.x), b0l = __float_as_uint(b0.y);
                uint32_t b1h = __float_as_uint(b1.x), b1l = __float_as_uint(b1.y);
                #pragma unroll
                for (int mt = 0; mt < 2; mt++) {
                    mma8(acc[mt][ot], al[mt], b0h, b1h);
                    mma8(acc[mt][ot], ah[mt], b0l, b1l);
                    mma8(acc[mt][ot], ah[mt], b0h, b1h);
                }
            }
        }
    }

    #pragma unroll
    for (int mt = 0; mt < 2; mt++)
        #pragma unroll
        for (int ot = 0; ot < 4; ot++) {
            int n = nblk + 32 * wn + 16 * mt + g;
            int o = oblk + 32 * wo + 8 * ot + 2 * quad;
            Yb[(long)o * NTOK + n]           = acc[mt][ot][0];
            Yb[(long)(o + 1) * NTOK + n]     = acc[mt][ot][1];
            Yb[(long)o * NTOK + n + 8]       = acc[mt][ot][2];
            Yb[(long)(o + 1) * NTOK + n + 8] = acc[mt][ot][3];
        }
}

// ---------------------------------------------------------------------------
// Norms: q2[b][h][n], k2[b][h][n]
// ---------------------------------------------------------------------------
__global__ void __launch_bounds__(256) norms_kernel()
{
    int idx = blockIdx.x * 256 + threadIdx.x;
    int n = idx & (NTOK - 1);
    int t = idx >> 12;
    int h = t & 7;
    int pb = t >> 3;
    int part = pb & 1;
    int b = pb >> 1;
    const float* p = g_qkv + ((long)(b * CQKV + part * CINNER + h * DH)) * NTOK + n;
    float s = 0.f;
    #pragma unroll
    for (int d = 0; d < DH; d++) { float v = p[(long)d * NTOK]; s = fmaf(v, v, s); }
    g_norms[(long)part * (NB * NH * NTOK) + (long)(b * NH + h) * NTOK + n] = s;
}

// ---------------------------------------------------------------------------
// Flash distance attention via mma.sync tf32.
// CTA = 256 threads = 8 warps; each warp owns 16 query rows (128 q / CTA).
// Fixed-shift softmax (scores bounded) -> no running max, no rescale.
// ---------------------------------------------------------------------------
__global__ void __launch_bounds__(256, 2) attn_mma_kernel()
{
    __shared__ uint32_t KF[8 * 516];
    __shared__ uint32_t VF[8 * 544];
    __shared__ float    k2s[64];

    const int tid  = threadIdx.x;
    const int wid  = tid >> 5;
    const int lane = tid & 31;
    const int quad = lane & 3;
    const int g    = lane >> 2;
    const int n0   = blockIdx.x * 128;
    const int h = blockIdx.y, b = blockIdx.z;
    const int bh = b * NH + h;

    const float* qb  = g_qkv + (long)(b * CQKV + h * DH) * NTOK;
    const float* kb  = g_qkv + (long)(b * CQKV + CINNER + h * DH) * NTOK;
    const float* vb  = g_qkv + (long)(b * CQKV + 2 * CINNER + h * DH) * NTOK;
    const float* k2g = g_norms + (long)NB * NH * NTOK + (long)bh * NTOK;

    const int i0 = n0 + wid * 16 + g;

    uint32_t aq[8][4];
    #pragma unroll
    for (int ks = 0; ks < 8; ks++) {
        int d = quad + 8 * ks;
        aq[ks][0] = tf32r(qb[(long)d * NTOK + i0]);
        aq[ks][1] = tf32r(qb[(long)d * NTOK + i0 + 8]);
        aq[ks][2] = tf32r(qb[(long)(d + 4) * NTOK + i0]);
        aq[ks][3] = tf32r(qb[(long)(d + 4) * NTOK + i0 + 8]);
    }
    const float q2a = g_norms[(long)bh * NTOK + i0];
    const float q2b = g_norms[(long)bh * NTOK + i0 + 8];

    constexpr float LOG2E  = 1.4426950408889634f;
    constexpr float NSHIFT = -12.0f * LOG2E;

    float o[8][4];
    #pragma unroll
    for (int nt = 0; nt < 8; nt++)
        #pragma unroll
        for (int r = 0; r < 4; r++) o[nt][r] = 0.f;
    float lsum0 = 0.f, lsum1 = 0.f;

    const int srcA = (lane & ~3) | (quad >> 1);
    const int srcB = srcA + 2;

    for (int kt = 0; kt < NTOK / 64; kt++) {
        const int nk = kt * 64;
        __syncthreads();

        // ---- stage K tile into fragment order (RNA-rounded) ----
        #pragma unroll
        for (int it = 0; it < 4; it++) {
            int idx = tid + it * 256;
            int d = idx >> 4, j4 = (idx & 15) << 2;
            float4 kv = *(const float4*)(kb + (long)d * NTOK + nk + j4);
            int base = (d >> 3) * 64 + (d & 3) * 2 + ((d >> 2) & 1);
            float v4[4] = {kv.x, kv.y, kv.z, kv.w};
            #pragma unroll
            for (int r = 0; r < 4; r++) {
                int j = j4 + r;
                KF[(j >> 3) * 516 + base + (j & 7) * 8] = tf32r(v4[r]);
            }
        }
        // ---- stage V tile (RNA-rounded) ----
        #pragma unroll
        for (int it = 0; it < 4; it++) {
            int idx = tid + it * 256;
            int dd = idx >> 4, j4 = (idx & 15) << 2;
            float4 vv = *(const float4*)(vb + (long)dd * NTOK + nk + j4);
            int base = (dd >> 3) * 544 + (dd & 7) * 8;
            float v4[4] = {vv.x, vv.y, vv.z, vv.w};
            #pragma unroll
            for (int r = 0; r < 4; r++) {
                int j = j4 + r;
                VF[base + (j >> 3) * 68 + (j & 3) * 2 + ((j >> 2) & 1)] = tf32r(v4[r]);
            }
        }
        if (tid < 64) k2s[tid] = k2g[nk + tid];
        __syncthreads();

        #pragma unroll
        for (int nt = 0; nt < 8; nt++) {
            // QK^T: two independent 4-mma chains to halve the dependency path
            float c[4] = {0.f, 0.f, 0.f, 0.f};
            float c2[4] = {0.f, 0.f, 0.f, 0.f};
            const uint32_t* kfp = KF + nt * 516 + lane * 2;
            #pragma unroll
            for (int ks = 0; ks < 4; ks++) {
                uint2 bb0 = *(const uint2*)(kfp + (2 * ks) * 64);
                uint2 bb1 = *(const uint2*)(kfp + (2 * ks + 1) * 64);
                mma8(c,  aq[2 * ks],     bb0.x, bb0.y);
                mma8(c2, aq[2 * ks + 1], bb1.x, bb1.y);
            }
            #pragma unroll
            for (int r = 0; r < 4; r++) c[r] += c2[r];

            float k2c0 = k2s[8 * nt + 2 * quad];
            float k2c1 = k2s[8 * nt + 2 * quad + 1];
            float p[4];
            {
                float d2, s;
                d2 = fmaxf(q2a + k2c0 - 2.f * c[0], 0.f);
                asm("sqrt.approx.f32 %0, %1;" : "=f"(s) : "f"(d2));
                asm("ex2.approx.f32 %0, %1;" : "=f"(p[0]) : "f"(fmaf(s, LOG2E, NSHIFT)));
                d2 = fmaxf(q2a + k2c1 - 2.f * c[1], 0.f);
                asm("sqrt.approx.f32 %0, %1;" : "=f"(s) : "f"(d2));
                asm("ex2.approx.f32 %0, %1;" : "=f"(p[1]) : "f"(fmaf(s, LOG2E, NSHIFT)));
                d2 = fmaxf(q2b + k2c0 - 2.f * c[2], 0.f);
                asm("sqrt.approx.f32 %0, %1;" : "=f"(s) : "f"(d2));
                asm("ex2.approx.f32 %0, %1;" : "=f"(p[2]) : "f"(fmaf(s, LOG2E, NSHIFT)));
                d2 = fmaxf(q2b + k2c1 - 2.f * c[3], 0.f);
                asm("sqrt.approx.f32 %0, %1;" : "=f"(s) : "f"(d2));
                asm("ex2.approx.f32 %0, %1;" : "=f"(p[3]) : "f"(fmaf(s, LOG2E, NSHIFT)));
            }
            lsum0 += p[0] + p[1];
            lsum1 += p[2] + p[3];

            // C-frag -> A-frag transpose via quad shuffles (RNA-rounded)
            uint32_t up0 = tf32r(p[0]), up1 = tf32r(p[1]);
            uint32_t up2 = tf32r(p[2]), up3 = tf32r(p[3]);
            uint32_t x0 = __shfl_sync(0xffffffffu, up0, srcA);
            uint32_t x1 = __shfl_sync(0xffffffffu, up1, srcA);
            uint32_t x2 = __shfl_sync(0xffffffffu, up2, srcA);
            uint32_t x3 = __shfl_sync(0xffffffffu, up3, srcA);
            uint32_t y0 = __shfl_sync(0xffffffffu, up0, srcB);
            uint32_t y1 = __shfl_sync(0xffffffffu, up1, srcB);
            uint32_t y2 = __shfl_sync(0xffffffffu, up2, srcB);
            uint32_t y3 = __shfl_sync(0xffffffffu, up3, srcB);
            uint32_t ap[4];
            ap[0] = (quad & 1) ? x1 : x0;
            ap[1] = (quad & 1) ? x3 : x2;
            ap[2] = (quad & 1) ? y1 : y0;
            ap[3] = (quad & 1) ? y3 : y2;

            const uint32_t* vfp = VF + nt * 68 + lane * 2;
            #pragma unroll
            for (int ddnt = 0; ddnt < 8; ddnt++) {
                uint2 vv = *(const uint2*)(vfp + ddnt * 544);
                mma8(o[ddnt], ap, vv.x, vv.y);
            }
        }
    }

    lsum0 += __shfl_xor_sync(0xffffffffu, lsum0, 1);
    lsum0 += __shfl_xor_sync(0xffffffffu, lsum0, 2);
    lsum1 += __shfl_xor_sync(0xffffffffu, lsum1, 1);
    lsum1 += __shfl_xor_sync(0xffffffffu, lsum1, 2);
    const float inv0 = 1.f / lsum0;
    const float inv1 = 1.f / lsum1;

    float* aob = g_ao + (long)(b * CINNER + h * DH) * NTOK;
    #pragma unroll
    for (int nt = 0; nt < 8; nt++) {
        int dd = 8 * nt + 2 * quad;
        aob[(long)dd * NTOK + i0]           = o[nt][0] * inv0;
        aob[(long)(dd + 1) * NTOK + i0]     = o[nt][1] * inv0;
        aob[(long)dd * NTOK + i0 + 8]       = o[nt][2] * inv1;
        aob[(long)(dd + 1) * NTOK + i0 + 8] = o[nt][3] * inv1;
    }
}

// ---------------------------------------------------------------------------
extern "C" void kernel_launch(void* const* d_in, const int* in_sizes, int n_in,
                              void* d_out, int out_size)
{
    (void)in_sizes; (void)n_in; (void)out_size;
    const float* fmap  = (const float*)d_in[0];   // [2,256,64,64]
    const float* w_qkv = (const float*)d_in[1];   // [1536,256]
    const float* w_out = (const float*)d_in[2];   // [256,512]
    float* out = (float*)d_out;                   // [2,256,64,64]

    void* qkvPtr = nullptr;
    void* aoPtr  = nullptr;
    cudaGetSymbolAddress(&qkvPtr, g_qkv);
    cudaGetSymbolAddress(&aoPtr,  g_ao);

    const int gemmSmem = (32 * 132 + 128 * 68) * (int)sizeof(float);  // 51712
    cudaFuncSetAttribute(gemm_tc_kernel,
                         cudaFuncAttributeMaxDynamicSharedMemorySize, gemmSmem);

    // K1: QKV projection  [1536,256] @ [2,256,4096] -> g_qkv (3xtf32)
    {
        dim3 grid(NTOK / 64, CQKV / 128, NB);
        gemm_tc_kernel<<<grid, 256, gemmSmem>>>(w_qkv, fmap, (float*)qkvPtr,
                                                CIN, (long)CIN * NTOK, (long)CQKV * NTOK);
    }
    // K2: norms
    norms_kernel<<<(NB * NH * 2 * NTOK) / 256, 256>>>();

    // K3: tensor-core (mma.sync tf32) attention
    {
        dim3 grid(NTOK / 128, NH, NB);
        attn_mma_kernel<<<grid, 256>>>();
    }
    // K4: output projection [256,512] @ [2,512,4096] -> out (3xtf32)
    {
        dim3 grid(NTOK / 64, CIN / 128, NB);
        gemm_tc_kernel<<<grid, 256, gemmSmem>>>(w_out, (const float*)aoPtr, out,
                                                CINNER, (long)CINNER * NTOK, (long)CIN * NTOK);
    }
}